// round 6
// baseline (speedup 1.0000x reference)
#include <cuda_runtime.h>

#define DD 4096
#define MM 1024
#define LL 8192
#define NB 592        // 148 SMs x 4 blocks: uniform residency (__launch_bounds__(256,4))
#define NSLICE 128    // colpass D-slices (32 rows each)

// ---------------- scratch (__device__ globals; no allocation allowed) --------
__device__ float g_sin[DD];
__device__ float g_sq[DD];
__device__ float g_qvec[MM];                 // p[m] * scale[m]
__device__ float g_u[DD];
__device__ float g_v[DD];
__device__ float g_part[3 * NSLICE * MM];    // colpass partials [acc][slice][m]
__device__ unsigned g_count = 0;             // barrier arrivals (monotone across replays)
__device__ unsigned g_phase = 0;             // barrier phase   (monotone across replays)
__device__ unsigned g_ctr[8];                // per-stage work queues (reset at kernel end)

// ---------------- grid-wide barrier (all NB blocks resident) ------------------
__device__ __forceinline__ void gridbar() {
    __syncthreads();
    if (threadIdx.x == 0) {
        __threadfence();                      // release
        volatile unsigned* ph = &g_phase;
        unsigned p = *ph;                     // snapshot before arriving
        unsigned old = atomicAdd(&g_count, 1u);
        if ((old + 1u) % NB == 0u) {
            atomicAdd(&g_phase, 1u);
        } else {
            while (*ph == p) __nanosleep(64);
        }
        __threadfence();                      // acquire
    }
    __syncthreads();
}

// ---------------- dynamic work queue ------------------------------------------
// Pre-check with __ldcg avoids the end-of-stage atomic herd; counter is monotone
// within a kernel, so a stale (low) read only costs one harmless extra atomic.
__device__ __forceinline__ int grab(int sid, int ntasks, int lane) {
    int t = ntasks;
    if (lane == 0) {
        unsigned c = __ldcg(&g_ctr[sid]);
        if ((int)c < ntasks) t = (int)atomicAdd(&g_ctr[sid], 1u);
    }
    return __shfl_sync(0xffffffffu, t, 0);
}

// ---------------- warp dot ----------------------------------------------------
// CS: evict-first on A (stream-once matrices; keeps mem/keys L2-resident).
// XC: 1 -> x kernel-constant (__ldg ok); 0 -> x written this kernel: plain loads.
template <int N4, int CS, int XC>
__device__ __forceinline__ float warp_dot(const float4* __restrict__ a4,
                                          const float4* x4, int lane) {
    float acc0 = 0.f, acc1 = 0.f;
#pragma unroll 8
    for (int i = 0; i < N4 / 32; i++) {
        float4 a = CS ? __ldcs(a4 + i * 32 + lane) : *(a4 + i * 32 + lane);
        float4 b = XC ? __ldg(x4 + i * 32 + lane) : *(x4 + i * 32 + lane);
        acc0 += a.x * b.x + a.y * b.y;
        acc1 += a.z * b.z + a.w * b.w;
    }
    float acc = acc0 + acc1;
#pragma unroll
    for (int o = 16; o; o >>= 1) acc += __shfl_down_sync(0xffffffffu, acc, o);
    return acc;
}

// ---------------- persistent mega-kernel -------------------------------------
__global__ __launch_bounds__(256, 4) void k_mega(
    const float* __restrict__ Fi, const float* __restrict__ Fq,
    const float* __restrict__ input, const float* __restrict__ query,
    const float* __restrict__ mem, const float* __restrict__ keys,
    const float* __restrict__ H, const float* __restrict__ R,
    const float* __restrict__ a_out, float* __restrict__ y)
{
    const int tid  = threadIdx.x;
    const int w    = tid >> 5;
    const int lane = tid & 31;
    const int bid  = blockIdx.x;

    __shared__ float red[8];
    __shared__ float bc;

    // ===== stage 1: g_sin = F_i@input, g_sq = F_q@query (268 MB) ==============
    {
        const float4* in4 = reinterpret_cast<const float4*>(input);
        const float4* qr4 = reinterpret_cast<const float4*>(query);
        int task;
        while ((task = grab(0, 2 * DD, lane)) < 2 * DD) {
            const int r = task & (DD - 1);
            const float4* a4 = reinterpret_cast<const float4*>(task < DD ? Fi : Fq)
                               + (size_t)r * (LL / 4);
            float acc = warp_dot<LL / 4, 1, 1>(a4, task < DD ? in4 : qr4, lane);
            if (lane == 0) (task < DD ? g_sin : g_sq)[r] = acc;
        }
    }
    gridbar();

    // ===== colpass: per-column gate logit, sumsq, attn logit (32 MB) ==========
    // 4096 warp-tasks: (slice 0..127) x (cchunk 0..31); task = 32 d-rows x 32 cols.
    {
        const float4* mem4 = reinterpret_cast<const float4*>(mem);
        const float4* key4 = reinterpret_cast<const float4*>(keys);
        int task;
        while ((task = grab(1, 4096, lane)) < 4096) {
            const int slice = task >> 5;
            const int cch   = task & 31;
            const int d0    = slice * 32;
            const int c4    = cch * 8 + (lane & 7);   // float4 column
            const int dsub  = lane >> 3;              // 0..3

            float4 ag  = make_float4(0.f, 0.f, 0.f, 0.f);
            float4 ass = make_float4(0.f, 0.f, 0.f, 0.f);
            float4 aq  = make_float4(0.f, 0.f, 0.f, 0.f);
#pragma unroll
            for (int j = 0; j < 8; j++) {
                const int d = d0 + dsub + j * 4;
                float4 mv = mem4[(size_t)d * (MM / 4) + c4];
                float4 kv = key4[(size_t)d * (MM / 4) + c4];
                float si = g_sin[d];
                float sq = g_sq[d];
                ag.x += si * (mv.x + kv.x);  ag.y += si * (mv.y + kv.y);
                ag.z += si * (mv.z + kv.z);  ag.w += si * (mv.w + kv.w);
                ass.x += mv.x * mv.x;  ass.y += mv.y * mv.y;
                ass.z += mv.z * mv.z;  ass.w += mv.w * mv.w;
                aq.x += sq * mv.x;  aq.y += sq * mv.y;
                aq.z += sq * mv.z;  aq.w += sq * mv.w;
            }
            // reduce across the 4 dsub groups (lanes l, l+8, l+16, l+24)
#pragma unroll
            for (int o = 8; o <= 16; o <<= 1) {
                ag.x  += __shfl_xor_sync(0xffffffffu, ag.x,  o);
                ag.y  += __shfl_xor_sync(0xffffffffu, ag.y,  o);
                ag.z  += __shfl_xor_sync(0xffffffffu, ag.z,  o);
                ag.w  += __shfl_xor_sync(0xffffffffu, ag.w,  o);
                ass.x += __shfl_xor_sync(0xffffffffu, ass.x, o);
                ass.y += __shfl_xor_sync(0xffffffffu, ass.y, o);
                ass.z += __shfl_xor_sync(0xffffffffu, ass.z, o);
                ass.w += __shfl_xor_sync(0xffffffffu, ass.w, o);
                aq.x  += __shfl_xor_sync(0xffffffffu, aq.x,  o);
                aq.y  += __shfl_xor_sync(0xffffffffu, aq.y,  o);
                aq.z  += __shfl_xor_sync(0xffffffffu, aq.z,  o);
                aq.w  += __shfl_xor_sync(0xffffffffu, aq.w,  o);
            }
            if (dsub == 0) {   // lanes 0..7 hold totals for c4 = cch*8 + lane
                float4* p4 = reinterpret_cast<float4*>(g_part);
                p4[(size_t)(0 * NSLICE + slice) * (MM / 4) + c4] = ag;
                p4[(size_t)(1 * NSLICE + slice) * (MM / 4) + c4] = ass;
                p4[(size_t)(2 * NSLICE + slice) * (MM / 4) + c4] = aq;
            }
        }
    }
    gridbar();

    // ===== finalize (block 0): gate -> scale -> softmax -> qvec ===============
    if (bid == 0) {
        const float4* p4 = reinterpret_cast<const float4*>(g_part);
        float4 ag  = make_float4(0.f, 0.f, 0.f, 0.f);
        float4 ass = make_float4(0.f, 0.f, 0.f, 0.f);
        float4 aq  = make_float4(0.f, 0.f, 0.f, 0.f);
#pragma unroll 8
        for (int s = 0; s < NSLICE; s++) {
            float4 v0 = p4[(0 * NSLICE + s) * (MM / 4) + tid];
            float4 v1 = p4[(1 * NSLICE + s) * (MM / 4) + tid];
            float4 v2 = p4[(2 * NSLICE + s) * (MM / 4) + tid];
            ag.x += v0.x; ag.y += v0.y; ag.z += v0.z; ag.w += v0.w;
            ass.x += v1.x; ass.y += v1.y; ass.z += v1.z; ass.w += v1.w;
            aq.x += v2.x; aq.y += v2.y; aq.z += v2.z; aq.w += v2.w;
        }
        float l[4], sc[4];
        {
            float agv[4]  = {ag.x, ag.y, ag.z, ag.w};
            float assv[4] = {ass.x, ass.y, ass.z, ass.w};
            float aqv[4]  = {aq.x, aq.y, aq.z, aq.w};
#pragma unroll
            for (int i = 0; i < 4; i++) {
                float g    = 1.f / (1.f + expf(-agv[i]));
                float onep = 1.f + g;                    // (1,2) > 0
                float nrm  = onep * sqrtf(assv[i]);      // ||mem_col*(1+g)||
                sc[i]      = onep / fmaxf(nrm, 1e-12f);
                l[i]       = sc[i] * aqv[i];
            }
        }
        float v = fmaxf(fmaxf(l[0], l[1]), fmaxf(l[2], l[3]));
#pragma unroll
        for (int o = 16; o; o >>= 1) v = fmaxf(v, __shfl_down_sync(0xffffffffu, v, o));
        if (lane == 0) red[w] = v;
        __syncthreads();
        if (tid == 0) {
            float mx = red[0];
#pragma unroll
            for (int i = 1; i < 8; i++) mx = fmaxf(mx, red[i]);
            bc = mx;
        }
        __syncthreads();
        const float mx = bc;
        float e[4];
#pragma unroll
        for (int i = 0; i < 4; i++) e[i] = expf(l[i] - mx);
        v = e[0] + e[1] + e[2] + e[3];
#pragma unroll
        for (int o = 16; o; o >>= 1) v += __shfl_down_sync(0xffffffffu, v, o);
        __syncthreads();
        if (lane == 0) red[w] = v;
        __syncthreads();
        if (tid == 0) {
            float sm = 0.f;
#pragma unroll
            for (int i = 0; i < 8; i++) sm += red[i];
            bc = sm;
        }
        __syncthreads();
        const float inv = 1.f / bc;
        float4 q;
        q.x = e[0] * inv * sc[0];
        q.y = e[1] * inv * sc[1];
        q.z = e[2] * inv * sc[2];
        q.w = e[3] * inv * sc[3];
        reinterpret_cast<float4*>(g_qvec)[tid] = q;
    }
    gridbar();

    // ===== u = memory_nodes @ qvec (16 MB, L2-hot) ============================
    {
        const float4* mem4 = reinterpret_cast<const float4*>(mem);
        const float4* x4   = reinterpret_cast<const float4*>(g_qvec);
        int task;
        while ((task = grab(2, DD, lane)) < DD) {
            float acc = warp_dot<MM / 4, 0, 0>(mem4 + (size_t)task * (MM / 4), x4, lane);
            if (lane == 0) g_u[task] = acc;
        }
    }
    gridbar();

    // ===== v = prelu(s_q + H @ u) (64 MB) =====================================
    {
        const float4* h4 = reinterpret_cast<const float4*>(H);
        const float4* x4 = reinterpret_cast<const float4*>(g_u);
        int task;
        while ((task = grab(3, DD, lane)) < DD) {
            float acc = warp_dot<DD / 4, 1, 0>(h4 + (size_t)task * (DD / 4), x4, lane);
            if (lane == 0) {
                float t = g_sq[task] + acc;
                float a = *a_out;
                g_v[task] = (t >= 0.f) ? t : a * t;
            }
        }
    }
    gridbar();

    // ===== y = R @ v (64 MB) ==================================================
    {
        const float4* r4 = reinterpret_cast<const float4*>(R);
        const float4* x4 = reinterpret_cast<const float4*>(g_v);
        int task;
        while ((task = grab(4, DD, lane)) < DD) {
            float acc = warp_dot<DD / 4, 1, 0>(r4 + (size_t)task * (DD / 4), x4, lane);
            if (lane == 0) y[task] = acc;
        }
    }

    // ===== reset queues for the next graph replay =============================
    gridbar();                                 // all grabs of all stages complete
    if (bid == 0 && tid < 8) g_ctr[tid] = 0;   // visible at next launch boundary
}

// ---------------- launch -----------------------------------------------------
extern "C" void kernel_launch(void* const* d_in, const int* in_sizes, int n_in,
                              void* d_out, int out_size) {
    const float* input = (const float*)d_in[0];
    const float* query = (const float*)d_in[1];
    const float* F_i   = (const float*)d_in[2];
    const float* F_q   = (const float*)d_in[3];
    const float* keys  = (const float*)d_in[4];
    const float* memn  = (const float*)d_in[5];
    // d_in[6..8] = U, V, W: dead code (cand unused) — skipped.
    const float* R     = (const float*)d_in[9];
    const float* H     = (const float*)d_in[10];
    // d_in[11] = a_mem: dead code — skipped.
    const float* a_out = (const float*)d_in[12];
    float* y = (float*)d_out;

    k_mega<<<NB, 256>>>(F_i, F_q, input, query, memn, keys, H, R, a_out, y);
}

// round 8
// speedup vs baseline: 1.4249x; 1.4249x over previous
#include <cuda_runtime.h>

#define DD 4096
#define MM 1024
#define LL 8192
#define NB 592        // 148 SMs x 4 blocks: uniform residency (__launch_bounds__(256,4))
#define NSLICE 128    // colpass D-slices (32 rows each)

// ---------------- scratch (__device__ globals; no allocation allowed) --------
__device__ float g_sin[DD];
__device__ float g_sq[DD];
__device__ float g_qvec[MM];                 // p[m] * scale[m]
__device__ float g_u[DD];
__device__ float g_v[DD];
__device__ float g_part[3 * NSLICE * MM];    // colpass partials [acc][slice][m]
__device__ unsigned g_count = 0;             // barrier arrivals (monotone across replays)
__device__ unsigned g_phase = 0;             // barrier phase   (monotone across replays)

// ---------------- grid-wide barrier (all NB blocks resident) ------------------
__device__ __forceinline__ void gridbar() {
    __syncthreads();
    if (threadIdx.x == 0) {
        __threadfence();                      // release
        volatile unsigned* ph = &g_phase;
        unsigned p = *ph;                     // snapshot before arriving
        unsigned old = atomicAdd(&g_count, 1u);
        if ((old + 1u) % NB == 0u) {
            atomicAdd(&g_phase, 1u);
        } else {
            while (*ph == p) __nanosleep(64);
        }
        __threadfence();                      // acquire
    }
    __syncthreads();
}

// 8-lane reduce of smem partials (lanes 0..7 participate)
__device__ __forceinline__ float red8(float v) {
    v += __shfl_down_sync(0x000000ffu, v, 4);
    v += __shfl_down_sync(0x000000ffu, v, 2);
    v += __shfl_down_sync(0x000000ffu, v, 1);
    return v;
}

// ---------------- persistent mega-kernel -------------------------------------
__global__ __launch_bounds__(256, 4) void k_mega(
    const float* __restrict__ Fi, const float* __restrict__ Fq,
    const float* __restrict__ input, const float* __restrict__ query,
    const float* __restrict__ mem, const float* __restrict__ keys,
    const float* __restrict__ H, const float* __restrict__ R,
    const float* __restrict__ a_out, float* __restrict__ y)
{
    const int tid  = threadIdx.x;
    const int w    = tid >> 5;
    const int lane = tid & 31;
    const int bid  = blockIdx.x;
    const int gwarp = bid * 8 + w;            // 0..4735

    __shared__ float sp[16][8];               // per-stage row partials [row_local][warp]
    __shared__ float red[8];
    __shared__ float bc;

    // ===== stage 1: g_sin = F_i@input, g_sq = F_q@query (268 MB) ==============
    // Balanced block split of 8192 rows -> 13 or 14 rows/block (tail ~1%).
    // Each row: 8 warps x 1024-elem contiguous segments (8 f4/lane, unrolled).
    {
        const int r0  = (bid * 2 * DD) / NB;
        const int r1  = ((bid + 1) * 2 * DD) / NB;
        const int cnt = r1 - r0;              // 13 or 14
        for (int rl = 0; rl < cnt; rl++) {
            const int row = r0 + rl;
            const int r   = row & (DD - 1);
            const float4* a4 = reinterpret_cast<const float4*>(row < DD ? Fi : Fq)
                               + (size_t)r * (LL / 4) + w * (LL / 32);
            const float4* x4 = reinterpret_cast<const float4*>(row < DD ? input : query)
                               + w * (LL / 32);
            float acc0 = 0.f, acc1 = 0.f;
#pragma unroll
            for (int i = 0; i < 8; i++) {     // 256 f4 per warp segment
                float4 a = __ldcs(a4 + i * 32 + lane);
                float4 b = __ldg(x4 + i * 32 + lane);
                acc0 += a.x * b.x + a.y * b.y;
                acc1 += a.z * b.z + a.w * b.w;
            }
            float acc = acc0 + acc1;
#pragma unroll
            for (int o = 16; o; o >>= 1) acc += __shfl_down_sync(0xffffffffu, acc, o);
            if (lane == 0) sp[rl][w] = acc;
        }
        __syncthreads();
        for (int rl = w; rl < cnt; rl += 8) {
            if (lane < 8) {
                float v = red8(sp[rl][lane]);
                if (lane == 0) {
                    const int row = r0 + rl;
                    (row < DD ? g_sin : g_sq)[row & (DD - 1)] = v;
                }
            }
        }
    }
    gridbar();

    // ===== colpass: per-column gate logit, sumsq, attn logit (32 MB) ==========
    // 4096 static warp-tasks (slice 0..127 x cchunk 0..31); warps 4096..4735 idle.
    if (gwarp < 4096) {
        const float4* mem4 = reinterpret_cast<const float4*>(mem);
        const float4* key4 = reinterpret_cast<const float4*>(keys);
        const int slice = gwarp >> 5;
        const int cch   = gwarp & 31;
        const int d0    = slice * 32;
        const int c4    = cch * 8 + (lane & 7);   // float4 column
        const int dsub  = lane >> 3;              // 0..3

        float4 ag  = make_float4(0.f, 0.f, 0.f, 0.f);
        float4 ass = make_float4(0.f, 0.f, 0.f, 0.f);
        float4 aq  = make_float4(0.f, 0.f, 0.f, 0.f);
#pragma unroll
        for (int j = 0; j < 8; j++) {
            const int d = d0 + dsub + j * 4;
            float4 mv = mem4[(size_t)d * (MM / 4) + c4];
            float4 kv = key4[(size_t)d * (MM / 4) + c4];
            float si = g_sin[d];
            float sq = g_sq[d];
            ag.x += si * (mv.x + kv.x);  ag.y += si * (mv.y + kv.y);
            ag.z += si * (mv.z + kv.z);  ag.w += si * (mv.w + kv.w);
            ass.x += mv.x * mv.x;  ass.y += mv.y * mv.y;
            ass.z += mv.z * mv.z;  ass.w += mv.w * mv.w;
            aq.x += sq * mv.x;  aq.y += sq * mv.y;
            aq.z += sq * mv.z;  aq.w += sq * mv.w;
        }
#pragma unroll
        for (int o = 8; o <= 16; o <<= 1) {
            ag.x  += __shfl_xor_sync(0xffffffffu, ag.x,  o);
            ag.y  += __shfl_xor_sync(0xffffffffu, ag.y,  o);
            ag.z  += __shfl_xor_sync(0xffffffffu, ag.z,  o);
            ag.w  += __shfl_xor_sync(0xffffffffu, ag.w,  o);
            ass.x += __shfl_xor_sync(0xffffffffu, ass.x, o);
            ass.y += __shfl_xor_sync(0xffffffffu, ass.y, o);
            ass.z += __shfl_xor_sync(0xffffffffu, ass.z, o);
            ass.w += __shfl_xor_sync(0xffffffffu, ass.w, o);
            aq.x  += __shfl_xor_sync(0xffffffffu, aq.x,  o);
            aq.y  += __shfl_xor_sync(0xffffffffu, aq.y,  o);
            aq.z  += __shfl_xor_sync(0xffffffffu, aq.z,  o);
            aq.w  += __shfl_xor_sync(0xffffffffu, aq.w,  o);
        }
        if (dsub == 0) {
            float4* p4 = reinterpret_cast<float4*>(g_part);
            p4[(size_t)(0 * NSLICE + slice) * (MM / 4) + c4] = ag;
            p4[(size_t)(1 * NSLICE + slice) * (MM / 4) + c4] = ass;
            p4[(size_t)(2 * NSLICE + slice) * (MM / 4) + c4] = aq;
        }
    }
    gridbar();

    // ===== finalize (block 0): gate -> scale -> softmax -> qvec ===============
    if (bid == 0) {
        const float4* p4 = reinterpret_cast<const float4*>(g_part);
        float4 ag  = make_float4(0.f, 0.f, 0.f, 0.f);
        float4 ass = make_float4(0.f, 0.f, 0.f, 0.f);
        float4 aq  = make_float4(0.f, 0.f, 0.f, 0.f);
#pragma unroll 8
        for (int s = 0; s < NSLICE; s++) {
            float4 v0 = p4[(0 * NSLICE + s) * (MM / 4) + tid];
            float4 v1 = p4[(1 * NSLICE + s) * (MM / 4) + tid];
            float4 v2 = p4[(2 * NSLICE + s) * (MM / 4) + tid];
            ag.x += v0.x; ag.y += v0.y; ag.z += v0.z; ag.w += v0.w;
            ass.x += v1.x; ass.y += v1.y; ass.z += v1.z; ass.w += v1.w;
            aq.x += v2.x; aq.y += v2.y; aq.z += v2.z; aq.w += v2.w;
        }
        float l[4], sc[4];
        {
            float agv[4]  = {ag.x, ag.y, ag.z, ag.w};
            float assv[4] = {ass.x, ass.y, ass.z, ass.w};
            float aqv[4]  = {aq.x, aq.y, aq.z, aq.w};
#pragma unroll
            for (int i = 0; i < 4; i++) {
                float g    = 1.f / (1.f + expf(-agv[i]));
                float onep = 1.f + g;                    // (1,2) > 0
                float nrm  = onep * sqrtf(assv[i]);      // ||mem_col*(1+g)||
                sc[i]      = onep / fmaxf(nrm, 1e-12f);
                l[i]       = sc[i] * aqv[i];
            }
        }
        float v = fmaxf(fmaxf(l[0], l[1]), fmaxf(l[2], l[3]));
#pragma unroll
        for (int o = 16; o; o >>= 1) v = fmaxf(v, __shfl_down_sync(0xffffffffu, v, o));
        if (lane == 0) red[w] = v;
        __syncthreads();
        if (tid == 0) {
            float mx = red[0];
#pragma unroll
            for (int i = 1; i < 8; i++) mx = fmaxf(mx, red[i]);
            bc = mx;
        }
        __syncthreads();
        const float mx = bc;
        float e[4];
#pragma unroll
        for (int i = 0; i < 4; i++) e[i] = expf(l[i] - mx);
        v = e[0] + e[1] + e[2] + e[3];
#pragma unroll
        for (int o = 16; o; o >>= 1) v += __shfl_down_sync(0xffffffffu, v, o);
        __syncthreads();
        if (lane == 0) red[w] = v;
        __syncthreads();
        if (tid == 0) {
            float sm = 0.f;
#pragma unroll
            for (int i = 0; i < 8; i++) sm += red[i];
            bc = sm;
        }
        __syncthreads();
        const float inv = 1.f / bc;
        float4 q;
        q.x = e[0] * inv * sc[0];
        q.y = e[1] * inv * sc[1];
        q.z = e[2] * inv * sc[2];
        q.w = e[3] * inv * sc[3];
        reinterpret_cast<float4*>(g_qvec)[tid] = q;
    }
    gridbar();

    // ===== u = memory_nodes @ qvec (16 MB, L2-hot) ============================
    // Balanced: 6/7 rows per block; row = 8 warps x 128-elem segments (1 f4/lane).
    {
        const int r0  = (bid * DD) / NB;
        const int r1  = ((bid + 1) * DD) / NB;
        const int cnt = r1 - r0;
        const float4* mem4 = reinterpret_cast<const float4*>(mem);
        const float4* x4   = reinterpret_cast<const float4*>(g_qvec);
        for (int rl = 0; rl < cnt; rl++) {
            const int row = r0 + rl;
            float4 a = mem4[(size_t)row * (MM / 4) + w * 32 + lane];
            float4 b = x4[w * 32 + lane];
            float acc = a.x * b.x + a.y * b.y + a.z * b.z + a.w * b.w;
#pragma unroll
            for (int o = 16; o; o >>= 1) acc += __shfl_down_sync(0xffffffffu, acc, o);
            if (lane == 0) sp[rl][w] = acc;
        }
        __syncthreads();
        for (int rl = w; rl < cnt; rl += 8) {
            if (lane < 8) {
                float v = red8(sp[rl][lane]);
                if (lane == 0) g_u[r0 + rl] = v;
            }
        }
    }
    gridbar();

    // ===== v = prelu(s_q + H @ u) (64 MB) =====================================
    {
        const int r0  = (bid * DD) / NB;
        const int r1  = ((bid + 1) * DD) / NB;
        const int cnt = r1 - r0;
        const float4* x4 = reinterpret_cast<const float4*>(g_u);
        for (int rl = 0; rl < cnt; rl++) {
            const int row = r0 + rl;
            const float4* a4 = reinterpret_cast<const float4*>(H)
                               + (size_t)row * (DD / 4) + w * (DD / 32);
            float acc0 = 0.f, acc1 = 0.f;
#pragma unroll
            for (int i = 0; i < 4; i++) {     // 128 f4 per warp segment
                float4 a = __ldcs(a4 + i * 32 + lane);
                float4 b = x4[w * (DD / 32) + i * 32 + lane];
                acc0 += a.x * b.x + a.y * b.y;
                acc1 += a.z * b.z + a.w * b.w;
            }
            float acc = acc0 + acc1;
#pragma unroll
            for (int o = 16; o; o >>= 1) acc += __shfl_down_sync(0xffffffffu, acc, o);
            if (lane == 0) sp[rl][w] = acc;
        }
        __syncthreads();
        for (int rl = w; rl < cnt; rl += 8) {
            if (lane < 8) {
                float v = red8(sp[rl][lane]);
                if (lane == 0) {
                    const int row = r0 + rl;
                    float t = g_sq[row] + v;
                    float a = *a_out;
                    g_v[row] = (t >= 0.f) ? t : a * t;
                }
            }
        }
    }
    gridbar();

    // ===== y = R @ v (64 MB) ==================================================
    {
        const int r0  = (bid * DD) / NB;
        const int r1  = ((bid + 1) * DD) / NB;
        const int cnt = r1 - r0;
        const float4* x4 = reinterpret_cast<const float4*>(g_v);
        for (int rl = 0; rl < cnt; rl++) {
            const int row = r0 + rl;
            const float4* a4 = reinterpret_cast<const float4*>(R)
                               + (size_t)row * (DD / 4) + w * (DD / 32);
            float acc0 = 0.f, acc1 = 0.f;
#pragma unroll
            for (int i = 0; i < 4; i++) {
                float4 a = __ldcs(a4 + i * 32 + lane);
                float4 b = x4[w * (DD / 32) + i * 32 + lane];
                acc0 += a.x * b.x + a.y * b.y;
                acc1 += a.z * b.z + a.w * b.w;
            }
            float acc = acc0 + acc1;
#pragma unroll
            for (int o = 16; o; o >>= 1) acc += __shfl_down_sync(0xffffffffu, acc, o);
            if (lane == 0) sp[rl][w] = acc;
        }
        __syncthreads();
        for (int rl = w; rl < cnt; rl += 8) {
            if (lane < 8) {
                float v = red8(sp[rl][lane]);
                if (lane == 0) y[r0 + rl] = v;
            }
        }
    }
}

// ---------------- launch -----------------------------------------------------
extern "C" void kernel_launch(void* const* d_in, const int* in_sizes, int n_in,
                              void* d_out, int out_size) {
    const float* input = (const float*)d_in[0];
    const float* query = (const float*)d_in[1];
    const float* F_i   = (const float*)d_in[2];
    const float* F_q   = (const float*)d_in[3];
    const float* keys  = (const float*)d_in[4];
    const float* memn  = (const float*)d_in[5];
    // d_in[6..8] = U, V, W: dead code (cand unused) — skipped.
    const float* R     = (const float*)d_in[9];
    const float* H     = (const float*)d_in[10];
    // d_in[11] = a_mem: dead code — skipped.
    const float* a_out = (const float*)d_in[12];
    float* y = (float*)d_out;

    k_mega<<<NB, 256>>>(F_i, F_q, input, query, memn, keys, H, R, a_out, y);
}

// round 9
// speedup vs baseline: 1.6104x; 1.1302x over previous
#include <cuda_runtime.h>

#define DD 4096
#define MM 1024
#define LL 8192
#define NB 592        // 148 SMs x 4 blocks: uniform residency (__launch_bounds__(256,4))

// ---------------- scratch (__device__ globals; no allocation allowed) --------
__device__ float g_sin[DD];
__device__ float g_sq[DD];
__device__ float g_qvec[MM];                 // p[m] * scale[m]
__device__ float g_u[DD];
__device__ float g_v[DD];
__device__ float g_acc[3 * MM];              // colpass accumulators [ag|ass|aq][m]
__device__ unsigned g_done = 0;              // colpass completion counter (reset per launch)
__device__ unsigned g_count = 0;             // barrier arrivals (monotone across replays)
__device__ unsigned g_phase = 0;             // barrier phase   (monotone across replays)

// ---------------- grid-wide barrier (all NB blocks resident) ------------------
__device__ __forceinline__ void gridbar() {
    __syncthreads();
    if (threadIdx.x == 0) {
        __threadfence();                      // release
        volatile unsigned* ph = &g_phase;
        unsigned p = *ph;                     // snapshot before arriving
        unsigned old = atomicAdd(&g_count, 1u);
        if ((old + 1u) % NB == 0u) {
            atomicAdd(&g_phase, 1u);
        } else {
            while (*ph == p) __nanosleep(64);
        }
        __threadfence();                      // acquire
    }
    __syncthreads();
}

__device__ __forceinline__ float red8(float v) {
    v += __shfl_down_sync(0x000000ffu, v, 4);
    v += __shfl_down_sync(0x000000ffu, v, 2);
    v += __shfl_down_sync(0x000000ffu, v, 1);
    return v;
}

// ---------------- persistent mega-kernel -------------------------------------
__global__ __launch_bounds__(256, 4) void k_mega(
    const float* __restrict__ Fi, const float* __restrict__ Fq,
    const float* __restrict__ input, const float* __restrict__ query,
    const float* __restrict__ mem, const float* __restrict__ keys,
    const float* __restrict__ H, const float* __restrict__ R,
    const float* __restrict__ a_out, float* __restrict__ y)
{
    const int tid  = threadIdx.x;
    const int w    = tid >> 5;
    const int lane = tid & 31;
    const int bid  = blockIdx.x;
    const int gwarp = bid * 8 + w;            // 0..4735

    __shared__ float4 sx4[2048];              // 32 KB x-vector buffer
    __shared__ float sp[16][8];               // row partials [row_local][warp]
    __shared__ float red[8];
    __shared__ float bc;

    // ===== stage 1: g_sin = F_i@input, g_sq = F_q@query (268 MB) ==============
    // Balanced block split of 8192 rows (13-14 rows/block); per range, x lives
    // in smem so each row costs only 8 independent LDG.128 per warp (high MLP).
    {
        const int r0 = (bid * 2 * DD) / NB;
        const int r1 = ((bid + 1) * 2 * DD) / NB;
#pragma unroll
        for (int range = 0; range < 2; range++) {
            const int a0 = range == 0 ? r0 : (r0 > DD ? r0 : DD);
            const int a1 = range == 0 ? (r1 < DD ? r1 : DD) : r1;
            if (a1 <= a0) continue;
            const float*  A  = range == 0 ? Fi : Fq;
            const float4* x4 = reinterpret_cast<const float4*>(range == 0 ? input : query);
            float* out = range == 0 ? g_sin : g_sq;

            // cooperative x load: 2048 f4 / 256 threads = 8 each
#pragma unroll
            for (int k = 0; k < 8; k++) sx4[tid + k * 256] = __ldg(x4 + tid + k * 256);
            __syncthreads();

            const int cnt = a1 - a0;
            for (int rl = 0; rl < cnt; rl++) {
                const int r = (a0 + rl) & (DD - 1);
                const float4* a4 = reinterpret_cast<const float4*>(A)
                                   + (size_t)r * (LL / 4) + w * 256;
                float acc0 = 0.f, acc1 = 0.f;
#pragma unroll
                for (int i = 0; i < 8; i++) {
                    float4 a = __ldcs(a4 + i * 32 + lane);
                    float4 b = sx4[w * 256 + i * 32 + lane];
                    acc0 += a.x * b.x + a.y * b.y;
                    acc1 += a.z * b.z + a.w * b.w;
                }
                float acc = acc0 + acc1;
#pragma unroll
                for (int o = 16; o; o >>= 1) acc += __shfl_down_sync(0xffffffffu, acc, o);
                if (lane == 0) sp[rl][w] = acc;
            }
            __syncthreads();
            for (int rl = w; rl < cnt; rl += 8) {
                if (lane < 8) {
                    float v = red8(sp[rl][lane]);
                    if (lane == 0) out[(a0 + rl) & (DD - 1)] = v;
                }
            }
            __syncthreads();
        }
    }
    gridbar();

    // ===== colpass: atomically accumulate gate logit, sumsq, attn logit ======
    // 4096 static warp-tasks (slice 0..127 x cchunk 0..31), 32 d-rows x 32 cols.
    if (gwarp < 4096) {
        const float4* mem4 = reinterpret_cast<const float4*>(mem);
        const float4* key4 = reinterpret_cast<const float4*>(keys);
        const int slice = gwarp >> 5;
        const int cch   = gwarp & 31;
        const int d0    = slice * 32;
        const int c4    = cch * 8 + (lane & 7);
        const int dsub  = lane >> 3;

        float4 ag  = make_float4(0.f, 0.f, 0.f, 0.f);
        float4 ass = make_float4(0.f, 0.f, 0.f, 0.f);
        float4 aq  = make_float4(0.f, 0.f, 0.f, 0.f);
#pragma unroll
        for (int j = 0; j < 8; j++) {
            const int d = d0 + dsub + j * 4;
            float4 mv = mem4[(size_t)d * (MM / 4) + c4];
            float4 kv = key4[(size_t)d * (MM / 4) + c4];
            float si = g_sin[d];
            float sq = g_sq[d];
            ag.x += si * (mv.x + kv.x);  ag.y += si * (mv.y + kv.y);
            ag.z += si * (mv.z + kv.z);  ag.w += si * (mv.w + kv.w);
            ass.x += mv.x * mv.x;  ass.y += mv.y * mv.y;
            ass.z += mv.z * mv.z;  ass.w += mv.w * mv.w;
            aq.x += sq * mv.x;  aq.y += sq * mv.y;
            aq.z += sq * mv.z;  aq.w += sq * mv.w;
        }
#pragma unroll
        for (int o = 8; o <= 16; o <<= 1) {
            ag.x  += __shfl_xor_sync(0xffffffffu, ag.x,  o);
            ag.y  += __shfl_xor_sync(0xffffffffu, ag.y,  o);
            ag.z  += __shfl_xor_sync(0xffffffffu, ag.z,  o);
            ag.w  += __shfl_xor_sync(0xffffffffu, ag.w,  o);
            ass.x += __shfl_xor_sync(0xffffffffu, ass.x, o);
            ass.y += __shfl_xor_sync(0xffffffffu, ass.y, o);
            ass.z += __shfl_xor_sync(0xffffffffu, ass.z, o);
            ass.w += __shfl_xor_sync(0xffffffffu, ass.w, o);
            aq.x  += __shfl_xor_sync(0xffffffffu, aq.x,  o);
            aq.y  += __shfl_xor_sync(0xffffffffu, aq.y,  o);
            aq.z  += __shfl_xor_sync(0xffffffffu, aq.z,  o);
            aq.w  += __shfl_xor_sync(0xffffffffu, aq.w,  o);
        }
        if (dsub == 0) {                       // lanes 0..7: 12 spread atomics each
            const int cb = c4 * 4;
            atomicAdd(&g_acc[0 * MM + cb + 0], ag.x);
            atomicAdd(&g_acc[0 * MM + cb + 1], ag.y);
            atomicAdd(&g_acc[0 * MM + cb + 2], ag.z);
            atomicAdd(&g_acc[0 * MM + cb + 3], ag.w);
            atomicAdd(&g_acc[1 * MM + cb + 0], ass.x);
            atomicAdd(&g_acc[1 * MM + cb + 1], ass.y);
            atomicAdd(&g_acc[1 * MM + cb + 2], ass.z);
            atomicAdd(&g_acc[1 * MM + cb + 3], ass.w);
            atomicAdd(&g_acc[2 * MM + cb + 0], aq.x);
            atomicAdd(&g_acc[2 * MM + cb + 1], aq.y);
            atomicAdd(&g_acc[2 * MM + cb + 2], aq.z);
            atomicAdd(&g_acc[2 * MM + cb + 3], aq.w);
        }
        __threadfence();                       // all lanes: order atomics before signal
        __syncwarp();
        if (lane == 0) atomicAdd(&g_done, 1u); // threadfenceReduction idiom
    }

    // ===== finalize (block 0, fused): wait colpass -> qvec, then reset ========
    if (bid == 0) {
        if (tid == 0) { while (__ldcg(&g_done) < 4096u) __nanosleep(32); }
        __syncthreads();

        const float4* a4p = reinterpret_cast<const float4*>(g_acc);
        float4 ag  = __ldcg(a4p + 0 * (MM / 4) + tid);
        float4 ass = __ldcg(a4p + 1 * (MM / 4) + tid);
        float4 aq  = __ldcg(a4p + 2 * (MM / 4) + tid);

        float l[4], sc[4];
        {
            float agv[4]  = {ag.x, ag.y, ag.z, ag.w};
            float assv[4] = {ass.x, ass.y, ass.z, ass.w};
            float aqv[4]  = {aq.x, aq.y, aq.z, aq.w};
#pragma unroll
            for (int i = 0; i < 4; i++) {
                float g    = 1.f / (1.f + expf(-agv[i]));
                float onep = 1.f + g;                    // (1,2) > 0
                float nrm  = onep * sqrtf(assv[i]);      // ||mem_col*(1+g)||
                sc[i]      = onep / fmaxf(nrm, 1e-12f);
                l[i]       = sc[i] * aqv[i];
            }
        }
        float v = fmaxf(fmaxf(l[0], l[1]), fmaxf(l[2], l[3]));
#pragma unroll
        for (int o = 16; o; o >>= 1) v = fmaxf(v, __shfl_down_sync(0xffffffffu, v, o));
        if (lane == 0) red[w] = v;
        __syncthreads();
        if (tid == 0) {
            float mx = red[0];
#pragma unroll
            for (int i = 1; i < 8; i++) mx = fmaxf(mx, red[i]);
            bc = mx;
        }
        __syncthreads();
        const float mx = bc;
        float e[4];
#pragma unroll
        for (int i = 0; i < 4; i++) e[i] = expf(l[i] - mx);
        v = e[0] + e[1] + e[2] + e[3];
#pragma unroll
        for (int o = 16; o; o >>= 1) v += __shfl_down_sync(0xffffffffu, v, o);
        __syncthreads();
        if (lane == 0) red[w] = v;
        __syncthreads();
        if (tid == 0) {
            float sm = 0.f;
#pragma unroll
            for (int i = 0; i < 8; i++) sm += red[i];
            bc = sm;
        }
        __syncthreads();
        const float inv = 1.f / bc;
        float4 q;
        q.x = e[0] * inv * sc[0];
        q.y = e[1] * inv * sc[1];
        q.z = e[2] * inv * sc[2];
        q.w = e[3] * inv * sc[3];
        reinterpret_cast<float4*>(g_qvec)[tid] = q;

        // reset accumulators + counter for the next graph replay (sole owner here)
        float4 z = make_float4(0.f, 0.f, 0.f, 0.f);
        float4* za = reinterpret_cast<float4*>(g_acc);
        za[0 * (MM / 4) + tid] = z;
        za[1 * (MM / 4) + tid] = z;
        za[2 * (MM / 4) + tid] = z;
        if (tid == 0) g_done = 0;
    }
    gridbar();

    // ===== u = memory_nodes @ qvec (16 MB, L2-hot) ============================
    {
        const int r0  = (bid * DD) / NB;
        const int cnt = ((bid + 1) * DD) / NB - r0;
        const float4* mem4 = reinterpret_cast<const float4*>(mem);
        const float4* x4   = reinterpret_cast<const float4*>(g_qvec);
        for (int rl = 0; rl < cnt; rl++) {
            float4 a = mem4[(size_t)(r0 + rl) * (MM / 4) + w * 32 + lane];
            float4 b = x4[w * 32 + lane];
            float acc = a.x * b.x + a.y * b.y + a.z * b.z + a.w * b.w;
#pragma unroll
            for (int o = 16; o; o >>= 1) acc += __shfl_down_sync(0xffffffffu, acc, o);
            if (lane == 0) sp[rl][w] = acc;
        }
        __syncthreads();
        for (int rl = w; rl < cnt; rl += 8) {
            if (lane < 8) {
                float v = red8(sp[rl][lane]);
                if (lane == 0) g_u[r0 + rl] = v;
            }
        }
    }
    gridbar();

    // ===== v = prelu(s_q + H @ u) (64 MB; 4 warps/row, 2 rows in flight) ======
    {
        const int r0  = (bid * DD) / NB;
        const int cnt = ((bid + 1) * DD) / NB - r0;
        // g_u (1024 f4) into smem
#pragma unroll
        for (int k = 0; k < 4; k++)
            sx4[tid + k * 256] = reinterpret_cast<const float4*>(g_u)[tid + k * 256];
        __syncthreads();

        const int half = w >> 2;   // 0: even rl, 1: odd rl
        const int wg   = w & 3;    // quarter-row segment
        for (int rl = half; rl < cnt; rl += 2) {
            const float4* a4 = reinterpret_cast<const float4*>(H)
                               + (size_t)(r0 + rl) * (DD / 4) + wg * 256;
            float acc0 = 0.f, acc1 = 0.f;
#pragma unroll
            for (int i = 0; i < 8; i++) {
                float4 a = __ldcs(a4 + i * 32 + lane);
                float4 b = sx4[wg * 256 + i * 32 + lane];
                acc0 += a.x * b.x + a.y * b.y;
                acc1 += a.z * b.z + a.w * b.w;
            }
            float acc = acc0 + acc1;
#pragma unroll
            for (int o = 16; o; o >>= 1) acc += __shfl_down_sync(0xffffffffu, acc, o);
            if (lane == 0) sp[rl][w] = acc;
        }
        __syncthreads();
        for (int rl = w; rl < cnt; rl += 8) {
            if (lane < 4) {
                float v = sp[rl][(rl & 1) * 4 + lane];
                v += __shfl_down_sync(0x0000000fu, v, 2);
                v += __shfl_down_sync(0x0000000fu, v, 1);
                if (lane == 0) {
                    const int row = r0 + rl;
                    float t = g_sq[row] + v;
                    float a = *a_out;
                    g_v[row] = (t >= 0.f) ? t : a * t;
                }
            }
        }
    }
    gridbar();

    // ===== y = R @ v (64 MB; same shape; R on default path -> L2-resident) ====
    {
        const int r0  = (bid * DD) / NB;
        const int cnt = ((bid + 1) * DD) / NB - r0;
#pragma unroll
        for (int k = 0; k < 4; k++)
            sx4[tid + k * 256] = reinterpret_cast<const float4*>(g_v)[tid + k * 256];
        __syncthreads();

        const int half = w >> 2;
        const int wg   = w & 3;
        for (int rl = half; rl < cnt; rl += 2) {
            const float4* a4 = reinterpret_cast<const float4*>(R)
                               + (size_t)(r0 + rl) * (DD / 4) + wg * 256;
            float acc0 = 0.f, acc1 = 0.f;
#pragma unroll
            for (int i = 0; i < 8; i++) {
                float4 a = *(a4 + i * 32 + lane);        // default caching: L2-resident
                float4 b = sx4[wg * 256 + i * 32 + lane];
                acc0 += a.x * b.x + a.y * b.y;
                acc1 += a.z * b.z + a.w * b.w;
            }
            float acc = acc0 + acc1;
#pragma unroll
            for (int o = 16; o; o >>= 1) acc += __shfl_down_sync(0xffffffffu, acc, o);
            if (lane == 0) sp[rl][w] = acc;
        }
        __syncthreads();
        for (int rl = w; rl < cnt; rl += 8) {
            if (lane < 4) {
                float v = sp[rl][(rl & 1) * 4 + lane];
                v += __shfl_down_sync(0x0000000fu, v, 2);
                v += __shfl_down_sync(0x0000000fu, v, 1);
                if (lane == 0) y[r0 + rl] = v;
            }
        }
    }
}

// ---------------- launch -----------------------------------------------------
extern "C" void kernel_launch(void* const* d_in, const int* in_sizes, int n_in,
                              void* d_out, int out_size) {
    const float* input = (const float*)d_in[0];
    const float* query = (const float*)d_in[1];
    const float* F_i   = (const float*)d_in[2];
    const float* F_q   = (const float*)d_in[3];
    const float* keys  = (const float*)d_in[4];
    const float* memn  = (const float*)d_in[5];
    // d_in[6..8] = U, V, W: dead code (cand unused) — skipped.
    const float* R     = (const float*)d_in[9];
    const float* H     = (const float*)d_in[10];
    // d_in[11] = a_mem: dead code — skipped.
    const float* a_out = (const float*)d_in[12];
    float* y = (float*)d_out;

    k_mega<<<NB, 256>>>(F_i, F_q, input, query, memn, keys, H, R, a_out, y);
}